// round 7
// baseline (speedup 1.0000x reference)
#include <cuda_runtime.h>
#include <math.h>
#include <stdint.h>

#define BATCH 8
#define NPTS  8192
#define MCL   512
#define NSAMP 64

#define OUT_XYZ 0
#define OUT_IDX (BATCH*MCL*3)
#define OUT_ATT (OUT_IDX + BATCH*MCL*NSAMP)
#define OUT_ORI (OUT_ATT + BATCH*MCL)

// transposed activation row stride (floats): 68 = 64 + pad (16B-aligned, conflict-light)
#define ST 68

__device__ int g_idx[BATCH * MCL * NSAMP];

typedef unsigned long long ull;

// ---------------- packed f32x2 helpers ----------------
__device__ __forceinline__ ull pack2dup(float a) {
    ull r;
    asm("mov.b64 %0, {%1, %1};" : "=l"(r) : "f"(a));
    return r;
}
__device__ __forceinline__ void unpack2(ull v, float& lo, float& hi) {
    asm("mov.b64 {%0, %1}, %2;" : "=f"(lo), "=f"(hi) : "l"(v));
}
__device__ __forceinline__ void fma2(ull& d, ull a, ull b) {
    asm("fma.rn.f32x2 %0, %1, %2, %0;" : "+l"(d) : "l"(a), "l"(b));
}
// ---------------- cp.async helpers ----------------
__device__ __forceinline__ void cp_async16(void* dst, const void* src) {
    unsigned d = (unsigned)__cvta_generic_to_shared(dst);
    asm volatile("cp.async.ca.shared.global [%0], [%1], 16;" :: "r"(d), "l"(src));
}
#define CP_COMMIT() asm volatile("cp.async.commit_group;")
#define CP_WAIT(n)  asm volatile("cp.async.wait_group %0;" :: "n"(n))

// =====================================================================
// Kernel 1: ball query (unchanged — passes, ~20us)
// =====================================================================
__global__ void __launch_bounds__(256)
ball_query_kernel(const float* __restrict__ xyz, float* __restrict__ out)
{
    extern __shared__ float smem[];
    float* sxyz = smem;
    int*   sidx = (int*)(smem + NPTS * 3);

    const int b     = blockIdx.x >> 4;
    const int chunk = blockIdx.x & 15;
    const float* xb = xyz + (size_t)b * NPTS * 3;

    const float4* xb4 = (const float4*)xb;
    for (int i = threadIdx.x; i < NPTS * 3 / 4; i += 256)
        ((float4*)sxyz)[i] = xb4[i];
    __syncthreads();

    const int m0 = chunk * 32;
    for (int i = threadIdx.x; i < 96; i += 256)
        out[OUT_XYZ + ((size_t)b * MCL + m0) * 3 + i] = sxyz[m0 * 3 + i];

    const int warp = threadIdx.x >> 5;
    const int lane = threadIdx.x & 31;
    int* wbuf = sidx + warp * NSAMP;

    for (int mi = warp; mi < 32; mi += 8) {
        const int m = m0 + mi;
        const float cx = sxyz[m * 3 + 0];
        const float cy = sxyz[m * 3 + 1];
        const float cz = sxyz[m * 3 + 2];
        int cnt = 0;
        for (int j = 0; j < NPTS; j += 32) {
            const int p = j + lane;
            float dx = __fsub_rn(cx, sxyz[p * 3 + 0]);
            float dy = __fsub_rn(cy, sxyz[p * 3 + 1]);
            float dz = __fsub_rn(cz, sxyz[p * 3 + 2]);
            float d2 = __fadd_rn(__fadd_rn(__fmul_rn(dx, dx), __fmul_rn(dy, dy)),
                                 __fmul_rn(dz, dz));
            bool valid = d2 < 4.0f;
            unsigned msk = __ballot_sync(0xffffffffu, valid);
            int pos = cnt + __popc(msk & ((1u << lane) - 1u));
            if (valid && pos < NSAMP) wbuf[pos] = p;
            cnt += __popc(msk);
            if (cnt >= NSAMP) break;
        }
        __syncwarp();
        const int first = wbuf[0];
        const int c = cnt < NSAMP ? cnt : NSAMP;
        const long base = ((long)b * MCL + m) * NSAMP;
        for (int k = lane; k < NSAMP; k += 32) {
            const int v = (k < c) ? wbuf[k] : first;
            g_idx[base + k] = v;
            out[OUT_IDX + base + k] = (float)v;
        }
        __syncwarp();
    }
}

// =====================================================================
// Kernel 2: fused MLP v3 — f32x2 packed over SAMPLES.
//  Activations transposed in SMEM (stride ST): A-operands are broadcast
//  LDS.128 loaded directly as packed pairs (no MOVs); weights dup-packed
//  once per k (shared by 8 samples). h3 = two 128-channel passes over
//  streamed W3 (acc stays 32 regs -> 3 CTAs/SM).
// SMEM (floats):
//   s_h2t 128*ST=8704 | s_red 2048 | s_hmax 256 | s_h4 128 | s_h5 64
//   union 6592: phase A: s_g 192 | s_h1t 64*ST=4352 | s_w2 2*1024
//               phase B: s_w3 2*2048
// total 17792 floats = 71168 B  (x3 CTA = 213.5 KB)
// =====================================================================
__global__ void __launch_bounds__(256, 3)
mlp_kernel(const float* __restrict__ xyz,
           const float* __restrict__ W1, const float* __restrict__ b1,
           const float* __restrict__ W2, const float* __restrict__ b2,
           const float* __restrict__ W3, const float* __restrict__ b3,
           const float* __restrict__ W4, const float* __restrict__ b4,
           const float* __restrict__ W5, const float* __restrict__ b5,
           const float* __restrict__ Wa, const float* __restrict__ ba,
           const float* __restrict__ Wo, const float* __restrict__ bo,
           float* __restrict__ out)
{
    extern __shared__ float sm[];
    float* s_h2t  = sm;                 // 8704
    float* s_red  = sm + 8704;          // 2048
    float* s_hmax = sm + 10752;         // 256
    float* s_h4   = sm + 11008;         // 128
    float* s_h5   = sm + 11136;         // 64
    float* s_u    = sm + 11200;         // 6592 union
    float* s_g    = s_u;                // 192
    float* s_h1t  = s_u + 192;          // 4352
    float* s_w2   = s_u + 4544;         // 2*1024
    float* s_w3   = s_u;                // 2*2048 (phase B)

    const int bm = blockIdx.x;
    const int b  = bm >> 9;
    const int m  = bm & (MCL - 1);
    const float* xb = xyz + (size_t)b * NPTS * 3;
    const int tid  = threadIdx.x;
    const int warp = tid >> 5;
    const int lane = tid & 31;
    const int s0   = warp * 8;          // this warp's 8 samples

    // prefetch W2 chunk 0 (8 rows x 128 = 1024 floats)
    cp_async16(s_w2 + tid * 4, W2 + tid * 4);
    CP_COMMIT();

    // ---- gather g = (xyz[idx] - center) * 0.5 ----
    if (tid < NSAMP) {
        const int p = g_idx[(size_t)bm * NSAMP + tid];
        const float cx = xb[m * 3 + 0], cy = xb[m * 3 + 1], cz = xb[m * 3 + 2];
        s_g[tid * 3 + 0] = (xb[p * 3 + 0] - cx) * 0.5f;
        s_g[tid * 3 + 1] = (xb[p * 3 + 1] - cy) * 0.5f;
        s_g[tid * 3 + 2] = (xb[p * 3 + 2] - cz) * 0.5f;
    }
    __syncthreads();

    // ---- h1 = relu(g @ W1 + b1), stored TRANSPOSED h1t[c][s] ----
    for (int o = tid; o < NSAMP * 64; o += 256) {
        const int s = o & 63, c = o >> 6;       // consecutive tid -> consecutive s
        float v = b1[c];
        v = fmaf(s_g[s * 3 + 0], W1[c], v);
        v = fmaf(s_g[s * 3 + 1], W1[64 + c], v);
        v = fmaf(s_g[s * 3 + 2], W1[128 + c], v);
        s_h1t[c * ST + s] = fmaxf(v, 0.0f);
    }
    // published by the first chunk's __syncthreads below

    // ---- h2 = relu(h1 @ W2 + b2): acc[4 sample-pairs][4 channels] ----
    ull acc2[4][4];
    {
        #pragma unroll
        for (int j = 0; j < 4; j++) {
            const ull bv = pack2dup(b2[lane + 32 * j]);
            #pragma unroll
            for (int i = 0; i < 4; i++) acc2[i][j] = bv;
        }

        for (int c = 0; c < 8; c++) {
            if (c + 1 < 8) {
                cp_async16(s_w2 + ((c + 1) & 1) * 1024 + tid * 4,
                           W2 + (c + 1) * 1024 + tid * 4);
                CP_COMMIT();
                CP_WAIT(1);
            } else {
                CP_WAIT(0);
            }
            __syncthreads();
            const float* wb = s_w2 + (c & 1) * 1024;
            #pragma unroll 4
            for (int r = 0; r < 8; r++) {
                const int k = c * 8 + r;
                const ulonglong2 qa = *(const ulonglong2*)(s_h1t + k * ST + s0);
                const ulonglong2 qb = *(const ulonglong2*)(s_h1t + k * ST + s0 + 4);
                #pragma unroll
                for (int j = 0; j < 4; j++) {
                    const ull w = pack2dup(wb[r * 128 + lane + 32 * j]);
                    fma2(acc2[0][j], qa.x, w);
                    fma2(acc2[1][j], qa.y, w);
                    fma2(acc2[2][j], qb.x, w);
                    fma2(acc2[3][j], qb.y, w);
                }
            }
            __syncthreads();
        }
    }

    // phase-A union memory now dead -> prefetch W3 chunk 0 (16 rows x cols[0:128))
    {
        #pragma unroll
        for (int t = 0; t < 2; t++) {
            const int idx = tid + t * 256;            // 0..511 float4s
            const int r = idx >> 5, c4 = idx & 31;
            cp_async16(s_w3 + idx * 4, W3 + (size_t)r * 256 + c4 * 4);
        }
        CP_COMMIT();
    }

    // h2 writeout (relu), transposed h2t[n][s] — warp-local s columns
    #pragma unroll
    for (int j = 0; j < 4; j++) {
        const int n = lane + 32 * j;
        float2* dst = (float2*)(s_h2t + n * ST + s0);
        #pragma unroll
        for (int i = 0; i < 4; i++) {
            float lo, hi;
            unpack2(acc2[i][j], lo, hi);
            dst[i] = make_float2(fmaxf(lo, 0.f), fmaxf(hi, 0.f));
        }
    }
    __syncwarp();   // h2t stripe produced & consumed by this warp only

    // ---- h3 = max_s(h2 @ W3 + b3): 2 passes of 128 channels, W3 streamed
    for (int half = 0; half < 2; half++) {
        ull acc[4][4];
        #pragma unroll
        for (int j = 0; j < 4; j++) {
            const ull bv = pack2dup(b3[half * 128 + lane + 32 * j]);
            #pragma unroll
            for (int i = 0; i < 4; i++) acc[i][j] = bv;
        }

        for (int c = 0; c < 8; c++) {               // 16 k-rows per chunk
            const int g1 = half * 8 + c + 1;        // next global chunk
            if (g1 < 16) {
                const int h2i = g1 >> 3, c2 = g1 & 7;
                float* dst = s_w3 + (g1 & 1) * 2048;
                #pragma unroll
                for (int t = 0; t < 2; t++) {
                    const int idx = tid + t * 256;
                    const int r = idx >> 5, c4 = idx & 31;
                    cp_async16(dst + idx * 4,
                               W3 + (size_t)(c2 * 16 + r) * 256 + h2i * 128 + c4 * 4);
                }
                CP_COMMIT();
                CP_WAIT(1);
            } else {
                CP_WAIT(0);
            }
            __syncthreads();

            const float* wb = s_w3 + ((half * 8 + c) & 1) * 2048;
            #pragma unroll 4
            for (int r = 0; r < 16; r++) {
                const int k = c * 16 + r;
                const ulonglong2 qa = *(const ulonglong2*)(s_h2t + k * ST + s0);
                const ulonglong2 qb = *(const ulonglong2*)(s_h2t + k * ST + s0 + 4);
                #pragma unroll
                for (int j = 0; j < 4; j++) {
                    const ull w = pack2dup(wb[r * 128 + lane + 32 * j]);
                    fma2(acc[0][j], qa.x, w);
                    fma2(acc[1][j], qa.y, w);
                    fma2(acc[2][j], qb.x, w);
                    fma2(acc[3][j], qb.y, w);
                }
            }
            __syncthreads();
        }

        // per-warp max over its 8 samples for this half's channels
        #pragma unroll
        for (int j = 0; j < 4; j++) {
            float mv = -3.402823466e38f;
            #pragma unroll
            for (int i = 0; i < 4; i++) {
                float lo, hi;
                unpack2(acc[i][j], lo, hi);
                mv = fmaxf(mv, fmaxf(lo, hi));
            }
            s_red[warp * 256 + half * 128 + lane + 32 * j] = mv;
        }
    }
    __syncthreads();

    // ---- cross-warp max + relu -> hmax[256] ----
    {
        float v = s_red[tid];
        #pragma unroll
        for (int w = 1; w < 8; w++) v = fmaxf(v, s_red[w * 256 + tid]);
        s_hmax[tid] = fmaxf(v, 0.0f);
    }
    __syncthreads();

    // ---- h4 = hmax @ W4 + b4  [128] ----
    if (tid < 128) {
        float acc = b4[tid];
        #pragma unroll 8
        for (int e = 0; e < 256; e++)
            acc = fmaf(s_hmax[e], W4[(size_t)e * 128 + tid], acc);
        s_h4[tid] = acc;
    }
    __syncthreads();

    // ---- h5 = h4 @ W5 + b5  [64] ----
    if (tid < 64) {
        float acc = b5[tid];
        #pragma unroll 8
        for (int d = 0; d < 128; d++)
            acc = fmaf(s_h4[d], W5[(size_t)d * 64 + tid], acc);
        s_h5[tid] = acc;
    }
    __syncthreads();

    // ---- heads: attention (softplus) + orientation (atan2) ----
    if (warp == 0) {
        const float h5a = s_h5[lane], h5b = s_h5[lane + 32];
        float pa = h5a * Wa[lane]         + h5b * Wa[lane + 32];
        float p0 = h5a * Wo[lane * 2 + 0] + h5b * Wo[(lane + 32) * 2 + 0];
        float p1 = h5a * Wo[lane * 2 + 1] + h5b * Wo[(lane + 32) * 2 + 1];
        #pragma unroll
        for (int off = 16; off; off >>= 1) {
            pa += __shfl_xor_sync(0xffffffffu, pa, off);
            p0 += __shfl_xor_sync(0xffffffffu, p0, off);
            p1 += __shfl_xor_sync(0xffffffffu, p1, off);
        }
        if (lane == 0) {
            const float x  = pa + ba[0];
            const float att = fmaxf(x, 0.0f) + log1pf(expf(-fabsf(x)));
            float o0 = p0 + bo[0];
            float o1 = p1 + bo[1];
            const float inv = 1.0f / sqrtf(fmaxf(o0 * o0 + o1 * o1, 1e-8f));
            o0 *= inv; o1 *= inv;
            out[OUT_ATT + bm] = att;
            out[OUT_ORI + bm] = atan2f(o1, o0);
        }
    }
}

// =====================================================================
extern "C" void kernel_launch(void* const* d_in, const int* in_sizes, int n_in,
                              void* d_out, int out_size)
{
    const float* xyz = (const float*)d_in[0];
    const float* W1  = (const float*)d_in[1];
    const float* b1  = (const float*)d_in[2];
    const float* W2  = (const float*)d_in[3];
    const float* b2  = (const float*)d_in[4];
    const float* W3  = (const float*)d_in[5];
    const float* b3  = (const float*)d_in[6];
    const float* W4  = (const float*)d_in[7];
    const float* b4  = (const float*)d_in[8];
    const float* W5  = (const float*)d_in[9];
    const float* b5  = (const float*)d_in[10];
    const float* Wa  = (const float*)d_in[11];
    const float* ba  = (const float*)d_in[12];
    const float* Wo  = (const float*)d_in[13];
    const float* bo  = (const float*)d_in[14];
    float* out = (float*)d_out;

    const int smem1 = NPTS * 3 * 4 + 8 * NSAMP * 4;   // 100352 B
    const int smem2 = 17792 * 4;                      // 71168 B

    cudaFuncSetAttribute(ball_query_kernel,
                         cudaFuncAttributeMaxDynamicSharedMemorySize, smem1);
    cudaFuncSetAttribute(mlp_kernel,
                         cudaFuncAttributeMaxDynamicSharedMemorySize, smem2);

    ball_query_kernel<<<BATCH * 16, 256, smem1>>>(xyz, out);
    mlp_kernel<<<BATCH * MCL, 256, smem2>>>(xyz, W1, b1, W2, b2, W3, b3,
                                            W4, b4, W5, b5, Wa, ba, Wo, bo, out);
}

// round 8
// speedup vs baseline: 1.0029x; 1.0029x over previous
#include <cuda_runtime.h>
#include <math.h>
#include <stdint.h>

#define BATCH 8
#define NPTS  8192
#define MCL   512
#define NSAMP 64

#define OUT_XYZ 0
#define OUT_IDX (BATCH*MCL*3)
#define OUT_ATT (OUT_IDX + BATCH*MCL*NSAMP)
#define OUT_ORI (OUT_ATT + BATCH*MCL)

// transposed activation row stride (floats): 68 = 64 + pad (16B-aligned, conflict-light)
#define ST 68

__device__ int g_idx[BATCH * MCL * NSAMP];

typedef unsigned long long ull;

// ---------------- packed f32x2 helpers ----------------
__device__ __forceinline__ ull pack2dup(float a) {
    ull r;
    asm("mov.b64 %0, {%1, %1};" : "=l"(r) : "f"(a));
    return r;
}
__device__ __forceinline__ void unpack2(ull v, float& lo, float& hi) {
    asm("mov.b64 {%0, %1}, %2;" : "=f"(lo), "=f"(hi) : "l"(v));
}
__device__ __forceinline__ void fma2(ull& d, ull a, ull b) {
    asm("fma.rn.f32x2 %0, %1, %2, %0;" : "+l"(d) : "l"(a), "l"(b));
}
// ---------------- cp.async helpers ----------------
__device__ __forceinline__ void cp_async16(void* dst, const void* src) {
    unsigned d = (unsigned)__cvta_generic_to_shared(dst);
    asm volatile("cp.async.ca.shared.global [%0], [%1], 16;" :: "r"(d), "l"(src));
}
#define CP_COMMIT() asm volatile("cp.async.commit_group;")
#define CP_WAIT(n)  asm volatile("cp.async.wait_group %0;" :: "n"(n))

// =====================================================================
// Kernel 1: ball query (unchanged — passes, ~20us)
// =====================================================================
__global__ void __launch_bounds__(256)
ball_query_kernel(const float* __restrict__ xyz, float* __restrict__ out)
{
    extern __shared__ float smem[];
    float* sxyz = smem;
    int*   sidx = (int*)(smem + NPTS * 3);

    const int b     = blockIdx.x >> 4;
    const int chunk = blockIdx.x & 15;
    const float* xb = xyz + (size_t)b * NPTS * 3;

    const float4* xb4 = (const float4*)xb;
    for (int i = threadIdx.x; i < NPTS * 3 / 4; i += 256)
        ((float4*)sxyz)[i] = xb4[i];
    __syncthreads();

    const int m0 = chunk * 32;
    for (int i = threadIdx.x; i < 96; i += 256)
        out[OUT_XYZ + ((size_t)b * MCL + m0) * 3 + i] = sxyz[m0 * 3 + i];

    const int warp = threadIdx.x >> 5;
    const int lane = threadIdx.x & 31;
    int* wbuf = sidx + warp * NSAMP;

    for (int mi = warp; mi < 32; mi += 8) {
        const int m = m0 + mi;
        const float cx = sxyz[m * 3 + 0];
        const float cy = sxyz[m * 3 + 1];
        const float cz = sxyz[m * 3 + 2];
        int cnt = 0;
        for (int j = 0; j < NPTS; j += 32) {
            const int p = j + lane;
            float dx = __fsub_rn(cx, sxyz[p * 3 + 0]);
            float dy = __fsub_rn(cy, sxyz[p * 3 + 1]);
            float dz = __fsub_rn(cz, sxyz[p * 3 + 2]);
            float d2 = __fadd_rn(__fadd_rn(__fmul_rn(dx, dx), __fmul_rn(dy, dy)),
                                 __fmul_rn(dz, dz));
            bool valid = d2 < 4.0f;
            unsigned msk = __ballot_sync(0xffffffffu, valid);
            int pos = cnt + __popc(msk & ((1u << lane) - 1u));
            if (valid && pos < NSAMP) wbuf[pos] = p;
            cnt += __popc(msk);
            if (cnt >= NSAMP) break;
        }
        __syncwarp();
        const int first = wbuf[0];
        const int c = cnt < NSAMP ? cnt : NSAMP;
        const long base = ((long)b * MCL + m) * NSAMP;
        for (int k = lane; k < NSAMP; k += 32) {
            const int v = (k < c) ? wbuf[k] : first;
            g_idx[base + k] = v;
            out[OUT_IDX + base + k] = (float)v;
        }
        __syncwarp();
    }
}

// =====================================================================
// Kernel 2: fused MLP v3 — f32x2 packed over SAMPLES.
//  Activations transposed in SMEM (stride ST): A-operands are broadcast
//  LDS.128 loaded directly as packed pairs (no MOVs); weights dup-packed
//  once per k (shared by 8 samples). h3 = two 128-channel passes over
//  streamed W3 (acc stays 32 regs -> 3 CTAs/SM).
// SMEM (floats):
//   s_h2t 128*ST=8704 | s_red 2048 | s_hmax 256 | s_h4 128 | s_h5 64
//   union 6592: phase A: s_g 192 | s_h1t 64*ST=4352 | s_w2 2*1024
//               phase B: s_w3 2*2048
// total 17792 floats = 71168 B  (x3 CTA = 213.5 KB)
// =====================================================================
__global__ void __launch_bounds__(256, 3)
mlp_kernel(const float* __restrict__ xyz,
           const float* __restrict__ W1, const float* __restrict__ b1,
           const float* __restrict__ W2, const float* __restrict__ b2,
           const float* __restrict__ W3, const float* __restrict__ b3,
           const float* __restrict__ W4, const float* __restrict__ b4,
           const float* __restrict__ W5, const float* __restrict__ b5,
           const float* __restrict__ Wa, const float* __restrict__ ba,
           const float* __restrict__ Wo, const float* __restrict__ bo,
           float* __restrict__ out)
{
    extern __shared__ float sm[];
    float* s_h2t  = sm;                 // 8704
    float* s_red  = sm + 8704;          // 2048
    float* s_hmax = sm + 10752;         // 256
    float* s_h4   = sm + 11008;         // 128
    float* s_h5   = sm + 11136;         // 64
    float* s_u    = sm + 11200;         // 6592 union
    float* s_g    = s_u;                // 192
    float* s_h1t  = s_u + 192;          // 4352
    float* s_w2   = s_u + 4544;         // 2*1024
    float* s_w3   = s_u;                // 2*2048 (phase B)

    const int bm = blockIdx.x;
    const int b  = bm >> 9;
    const int m  = bm & (MCL - 1);
    const float* xb = xyz + (size_t)b * NPTS * 3;
    const int tid  = threadIdx.x;
    const int warp = tid >> 5;
    const int lane = tid & 31;
    const int s0   = warp * 8;          // this warp's 8 samples

    // prefetch W2 chunk 0 (8 rows x 128 = 1024 floats)
    cp_async16(s_w2 + tid * 4, W2 + tid * 4);
    CP_COMMIT();

    // ---- gather g = (xyz[idx] - center) * 0.5 ----
    if (tid < NSAMP) {
        const int p = g_idx[(size_t)bm * NSAMP + tid];
        const float cx = xb[m * 3 + 0], cy = xb[m * 3 + 1], cz = xb[m * 3 + 2];
        s_g[tid * 3 + 0] = (xb[p * 3 + 0] - cx) * 0.5f;
        s_g[tid * 3 + 1] = (xb[p * 3 + 1] - cy) * 0.5f;
        s_g[tid * 3 + 2] = (xb[p * 3 + 2] - cz) * 0.5f;
    }
    __syncthreads();

    // ---- h1 = relu(g @ W1 + b1), stored TRANSPOSED h1t[c][s] ----
    for (int o = tid; o < NSAMP * 64; o += 256) {
        const int s = o & 63, c = o >> 6;       // consecutive tid -> consecutive s
        float v = b1[c];
        v = fmaf(s_g[s * 3 + 0], W1[c], v);
        v = fmaf(s_g[s * 3 + 1], W1[64 + c], v);
        v = fmaf(s_g[s * 3 + 2], W1[128 + c], v);
        s_h1t[c * ST + s] = fmaxf(v, 0.0f);
    }
    // published by the first chunk's __syncthreads below

    // ---- h2 = relu(h1 @ W2 + b2): acc[4 sample-pairs][4 channels] ----
    ull acc2[4][4];
    {
        #pragma unroll
        for (int j = 0; j < 4; j++) {
            const ull bv = pack2dup(b2[lane + 32 * j]);
            #pragma unroll
            for (int i = 0; i < 4; i++) acc2[i][j] = bv;
        }

        for (int c = 0; c < 8; c++) {
            if (c + 1 < 8) {
                cp_async16(s_w2 + ((c + 1) & 1) * 1024 + tid * 4,
                           W2 + (c + 1) * 1024 + tid * 4);
                CP_COMMIT();
                CP_WAIT(1);
            } else {
                CP_WAIT(0);
            }
            __syncthreads();
            const float* wb = s_w2 + (c & 1) * 1024;
            #pragma unroll 4
            for (int r = 0; r < 8; r++) {
                const int k = c * 8 + r;
                const ulonglong2 qa = *(const ulonglong2*)(s_h1t + k * ST + s0);
                const ulonglong2 qb = *(const ulonglong2*)(s_h1t + k * ST + s0 + 4);
                #pragma unroll
                for (int j = 0; j < 4; j++) {
                    const ull w = pack2dup(wb[r * 128 + lane + 32 * j]);
                    fma2(acc2[0][j], qa.x, w);
                    fma2(acc2[1][j], qa.y, w);
                    fma2(acc2[2][j], qb.x, w);
                    fma2(acc2[3][j], qb.y, w);
                }
            }
            __syncthreads();
        }
    }

    // phase-A union memory now dead -> prefetch W3 chunk 0 (16 rows x cols[0:128))
    {
        #pragma unroll
        for (int t = 0; t < 2; t++) {
            const int idx = tid + t * 256;            // 0..511 float4s
            const int r = idx >> 5, c4 = idx & 31;
            cp_async16(s_w3 + idx * 4, W3 + (size_t)r * 256 + c4 * 4);
        }
        CP_COMMIT();
    }

    // h2 writeout (relu), transposed h2t[n][s] — warp-local s columns
    #pragma unroll
    for (int j = 0; j < 4; j++) {
        const int n = lane + 32 * j;
        float2* dst = (float2*)(s_h2t + n * ST + s0);
        #pragma unroll
        for (int i = 0; i < 4; i++) {
            float lo, hi;
            unpack2(acc2[i][j], lo, hi);
            dst[i] = make_float2(fmaxf(lo, 0.f), fmaxf(hi, 0.f));
        }
    }
    __syncwarp();   // h2t stripe produced & consumed by this warp only

    // ---- h3 = max_s(h2 @ W3 + b3): 2 passes of 128 channels, W3 streamed
    for (int half = 0; half < 2; half++) {
        ull acc[4][4];
        #pragma unroll
        for (int j = 0; j < 4; j++) {
            const ull bv = pack2dup(b3[half * 128 + lane + 32 * j]);
            #pragma unroll
            for (int i = 0; i < 4; i++) acc[i][j] = bv;
        }

        for (int c = 0; c < 8; c++) {               // 16 k-rows per chunk
            const int g1 = half * 8 + c + 1;        // next global chunk
            if (g1 < 16) {
                const int h2i = g1 >> 3, c2 = g1 & 7;
                float* dst = s_w3 + (g1 & 1) * 2048;
                #pragma unroll
                for (int t = 0; t < 2; t++) {
                    const int idx = tid + t * 256;
                    const int r = idx >> 5, c4 = idx & 31;
                    cp_async16(dst + idx * 4,
                               W3 + (size_t)(c2 * 16 + r) * 256 + h2i * 128 + c4 * 4);
                }
                CP_COMMIT();
                CP_WAIT(1);
            } else {
                CP_WAIT(0);
            }
            __syncthreads();

            const float* wb = s_w3 + ((half * 8 + c) & 1) * 2048;
            #pragma unroll 4
            for (int r = 0; r < 16; r++) {
                const int k = c * 16 + r;
                const ulonglong2 qa = *(const ulonglong2*)(s_h2t + k * ST + s0);
                const ulonglong2 qb = *(const ulonglong2*)(s_h2t + k * ST + s0 + 4);
                #pragma unroll
                for (int j = 0; j < 4; j++) {
                    const ull w = pack2dup(wb[r * 128 + lane + 32 * j]);
                    fma2(acc[0][j], qa.x, w);
                    fma2(acc[1][j], qa.y, w);
                    fma2(acc[2][j], qb.x, w);
                    fma2(acc[3][j], qb.y, w);
                }
            }
            __syncthreads();
        }

        // per-warp max over its 8 samples for this half's channels
        #pragma unroll
        for (int j = 0; j < 4; j++) {
            float mv = -3.402823466e38f;
            #pragma unroll
            for (int i = 0; i < 4; i++) {
                float lo, hi;
                unpack2(acc[i][j], lo, hi);
                mv = fmaxf(mv, fmaxf(lo, hi));
            }
            s_red[warp * 256 + half * 128 + lane + 32 * j] = mv;
        }
    }
    __syncthreads();

    // ---- cross-warp max + relu -> hmax[256] ----
    {
        float v = s_red[tid];
        #pragma unroll
        for (int w = 1; w < 8; w++) v = fmaxf(v, s_red[w * 256 + tid]);
        s_hmax[tid] = fmaxf(v, 0.0f);
    }
    __syncthreads();

    // ---- h4 = hmax @ W4 + b4  [128] ----
    if (tid < 128) {
        float acc = b4[tid];
        #pragma unroll 8
        for (int e = 0; e < 256; e++)
            acc = fmaf(s_hmax[e], W4[(size_t)e * 128 + tid], acc);
        s_h4[tid] = acc;
    }
    __syncthreads();

    // ---- h5 = h4 @ W5 + b5  [64] ----
    if (tid < 64) {
        float acc = b5[tid];
        #pragma unroll 8
        for (int d = 0; d < 128; d++)
            acc = fmaf(s_h4[d], W5[(size_t)d * 64 + tid], acc);
        s_h5[tid] = acc;
    }
    __syncthreads();

    // ---- heads: attention (softplus) + orientation (atan2) ----
    if (warp == 0) {
        const float h5a = s_h5[lane], h5b = s_h5[lane + 32];
        float pa = h5a * Wa[lane]         + h5b * Wa[lane + 32];
        float p0 = h5a * Wo[lane * 2 + 0] + h5b * Wo[(lane + 32) * 2 + 0];
        float p1 = h5a * Wo[lane * 2 + 1] + h5b * Wo[(lane + 32) * 2 + 1];
        #pragma unroll
        for (int off = 16; off; off >>= 1) {
            pa += __shfl_xor_sync(0xffffffffu, pa, off);
            p0 += __shfl_xor_sync(0xffffffffu, p0, off);
            p1 += __shfl_xor_sync(0xffffffffu, p1, off);
        }
        if (lane == 0) {
            const float x  = pa + ba[0];
            const float att = fmaxf(x, 0.0f) + log1pf(expf(-fabsf(x)));
            float o0 = p0 + bo[0];
            float o1 = p1 + bo[1];
            const float inv = 1.0f / sqrtf(fmaxf(o0 * o0 + o1 * o1, 1e-8f));
            o0 *= inv; o1 *= inv;
            out[OUT_ATT + bm] = att;
            out[OUT_ORI + bm] = atan2f(o1, o0);
        }
    }
}

// =====================================================================
extern "C" void kernel_launch(void* const* d_in, const int* in_sizes, int n_in,
                              void* d_out, int out_size)
{
    const float* xyz = (const float*)d_in[0];
    const float* W1  = (const float*)d_in[1];
    const float* b1  = (const float*)d_in[2];
    const float* W2  = (const float*)d_in[3];
    const float* b2  = (const float*)d_in[4];
    const float* W3  = (const float*)d_in[5];
    const float* b3  = (const float*)d_in[6];
    const float* W4  = (const float*)d_in[7];
    const float* b4  = (const float*)d_in[8];
    const float* W5  = (const float*)d_in[9];
    const float* b5  = (const float*)d_in[10];
    const float* Wa  = (const float*)d_in[11];
    const float* ba  = (const float*)d_in[12];
    const float* Wo  = (const float*)d_in[13];
    const float* bo  = (const float*)d_in[14];
    float* out = (float*)d_out;

    const int smem1 = NPTS * 3 * 4 + 8 * NSAMP * 4;   // 100352 B
    const int smem2 = 17792 * 4;                      // 71168 B

    cudaFuncSetAttribute(ball_query_kernel,
                         cudaFuncAttributeMaxDynamicSharedMemorySize, smem1);
    cudaFuncSetAttribute(mlp_kernel,
                         cudaFuncAttributeMaxDynamicSharedMemorySize, smem2);

    ball_query_kernel<<<BATCH * 16, 256, smem1>>>(xyz, out);
    mlp_kernel<<<BATCH * MCL, 256, smem2>>>(xyz, W1, b1, W2, b2, W3, b3,
                                            W4, b4, W5, b5, Wa, ba, Wo, bo, out);
}

// round 14
// speedup vs baseline: 1.3873x; 1.3833x over previous
#include <cuda_runtime.h>
#include <cuda_bf16.h>
#include <math.h>
#include <stdint.h>

#define BATCH 8
#define NPTS  8192
#define MCL   512
#define NSAMP 64

#define OUT_XYZ 0
#define OUT_IDX (BATCH*MCL*3)
#define OUT_ATT (OUT_IDX + BATCH*MCL*NSAMP)
#define OUT_ORI (OUT_ATT + BATCH*MCL)

__device__ int g_idx[BATCH * MCL * NSAMP];
// transposed bf16 hi/lo weight images: B2t[n][k] (128x64), B3t[n][k] (256x128)
__device__ unsigned char g_B2thi[16384];
__device__ unsigned char g_B2tlo[16384];
__device__ unsigned char g_B3thi[65536];
__device__ unsigned char g_B3tlo[65536];

// ---------------- helpers ----------------
__device__ __forceinline__ uint32_t smem_u32(const void* p) {
    uint32_t a;
    asm("{ .reg .u64 t; cvta.to.shared.u64 t, %1; cvt.u32.u64 %0, t; }" : "=r"(a) : "l"(p));
    return a;
}
__device__ __forceinline__ void cp16(uint32_t dst, const void* src) {
    asm volatile("cp.async.ca.shared.global [%0], [%1], 16;" :: "r"(dst), "l"(src));
}
#define CP_COMMIT() asm volatile("cp.async.commit_group;")
#define CP_WAIT(n)  asm volatile("cp.async.wait_group %0;" :: "n"(n))

__device__ __forceinline__ void mma16816(float* d, const uint32_t* a, const uint32_t* b) {
    asm volatile("mma.sync.aligned.m16n8k16.row.col.f32.bf16.bf16.f32 "
        "{%0,%1,%2,%3}, {%4,%5,%6,%7}, {%8,%9}, {%0,%1,%2,%3};"
        : "+f"(d[0]), "+f"(d[1]), "+f"(d[2]), "+f"(d[3])
        : "r"(a[0]), "r"(a[1]), "r"(a[2]), "r"(a[3]), "r"(b[0]), "r"(b[1]));
}
__device__ __forceinline__ void split2(float v0, float v1, uint32_t& hi, uint32_t& lo) {
    __nv_bfloat16 h0 = __float2bfloat16_rn(v0);
    __nv_bfloat16 h1 = __float2bfloat16_rn(v1);
    __nv_bfloat16 l0 = __float2bfloat16_rn(v0 - __bfloat162float(h0));
    __nv_bfloat16 l1 = __float2bfloat16_rn(v1 - __bfloat162float(h1));
    hi = (uint32_t)__bfloat16_as_ushort(h0) | ((uint32_t)__bfloat16_as_ushort(h1) << 16);
    lo = (uint32_t)__bfloat16_as_ushort(l0) | ((uint32_t)__bfloat16_as_ushort(l1) << 16);
}

// SMEM byte offsets (mlp kernel). Padded strides: A2/B2t rows 144 B (72 bf16),
// A3/B3 rows 272 B (136 bf16) — conflict-free fragment LDS.
#define A2HI_B   0          // 128*144 = 18432   (region1: reused as B3 bufs)
#define A2LO_B   18432
#define B2HI_B   36864
#define B2LO_B   55296      // region1 end 73728
#define BUF0_B   0          // B3 chunk buf0: hi 0..17408, lo 17408..34816
#define BUF1_B   34816      // buf1: hi..52224, lo..69632
#define A3HI_B   73728      // 128*272 = 34816
#define A3LO_B   108544     // end 143360
#define RED_B    143360     // 8*256 f = 8192
#define HMAX_B   151552     // 2*256 f
#define H4_B     153600     // 2*128 f
#define H5_B     154624     // 2*64 f
#define GXYZ_B   155136     // 128*3 f
#define W1S_B    156672     // 192 f
#define B1S_B    157440     // 64 f
#define B2S_B    157696     // 128 f
#define B3S_B    158208     // 256 f
#define SMEM_MLP 159232

// =====================================================================
// Kernel 0: build transposed bf16 hi/lo weight images
// =====================================================================
__global__ void __launch_bounds__(256)
prep_weights(const float* __restrict__ W2, const float* __restrict__ W3)
{
    const int i = blockIdx.x * 256 + threadIdx.x;
    if (i < 8192) {                       // B2t[n][k] = W2[k][n], n<128, k<64
        const int n = i >> 6, k = i & 63;
        const float v = W2[k * 128 + n];
        __nv_bfloat16 h = __float2bfloat16_rn(v);
        __nv_bfloat16 l = __float2bfloat16_rn(v - __bfloat162float(h));
        *(unsigned short*)(g_B2thi + (n * 64 + k) * 2) = __bfloat16_as_ushort(h);
        *(unsigned short*)(g_B2tlo + (n * 64 + k) * 2) = __bfloat16_as_ushort(l);
    } else if (i < 8192 + 32768) {        // B3t[n][k] = W3[k][n], n<256, k<128
        const int e = i - 8192;
        const int n = e >> 7, k = e & 127;
        const float v = W3[k * 256 + n];
        __nv_bfloat16 h = __float2bfloat16_rn(v);
        __nv_bfloat16 l = __float2bfloat16_rn(v - __bfloat162float(h));
        *(unsigned short*)(g_B3thi + (n * 128 + k) * 2) = __bfloat16_as_ushort(h);
        *(unsigned short*)(g_B3tlo + (n * 128 + k) * 2) = __bfloat16_as_ushort(l);
    }
}

// =====================================================================
// Kernel 1: ball query (unchanged — passes)
// =====================================================================
__global__ void __launch_bounds__(256)
ball_query_kernel(const float* __restrict__ xyz, float* __restrict__ out)
{
    extern __shared__ float smem[];
    float* sxyz = smem;
    int*   sidx = (int*)(smem + NPTS * 3);

    const int b     = blockIdx.x >> 4;
    const int chunk = blockIdx.x & 15;
    const float* xb = xyz + (size_t)b * NPTS * 3;

    const float4* xb4 = (const float4*)xb;
    for (int i = threadIdx.x; i < NPTS * 3 / 4; i += 256)
        ((float4*)sxyz)[i] = xb4[i];
    __syncthreads();

    const int m0 = chunk * 32;
    for (int i = threadIdx.x; i < 96; i += 256)
        out[OUT_XYZ + ((size_t)b * MCL + m0) * 3 + i] = sxyz[m0 * 3 + i];

    const int warp = threadIdx.x >> 5;
    const int lane = threadIdx.x & 31;
    int* wbuf = sidx + warp * NSAMP;

    for (int mi = warp; mi < 32; mi += 8) {
        const int m = m0 + mi;
        const float cx = sxyz[m * 3 + 0];
        const float cy = sxyz[m * 3 + 1];
        const float cz = sxyz[m * 3 + 2];
        int cnt = 0;
        for (int j = 0; j < NPTS; j += 32) {
            const int p = j + lane;
            float dx = __fsub_rn(cx, sxyz[p * 3 + 0]);
            float dy = __fsub_rn(cy, sxyz[p * 3 + 1]);
            float dz = __fsub_rn(cz, sxyz[p * 3 + 2]);
            float d2 = __fadd_rn(__fadd_rn(__fmul_rn(dx, dx), __fmul_rn(dy, dy)),
                                 __fmul_rn(dz, dz));
            bool valid = d2 < 4.0f;
            unsigned msk = __ballot_sync(0xffffffffu, valid);
            int pos = cnt + __popc(msk & ((1u << lane) - 1u));
            if (valid && pos < NSAMP) wbuf[pos] = p;
            cnt += __popc(msk);
            if (cnt >= NSAMP) break;
        }
        __syncwarp();
        const int first = wbuf[0];
        const int c = cnt < NSAMP ? cnt : NSAMP;
        const long base = ((long)b * MCL + m) * NSAMP;
        for (int k = lane; k < NSAMP; k += 32) {
            const int v = (k < c) ? wbuf[k] : first;
            g_idx[base + k] = v;
            out[OUT_IDX + base + k] = (float)v;
        }
        __syncwarp();
    }
}

// =====================================================================
// Kernel 2: fused MLP on mma.sync bf16 (hi/lo split, fp32 accumulate).
// 2 centers/block (M=128), 8 warps x 16-row tiles.
// h2: 16x128x64 per warp. h3: 4 N-chunks of 64, K=128, W3 streamed.
// =====================================================================
__global__ void __launch_bounds__(256, 1)
mlp_kernel(const float* __restrict__ xyz,
           const float* __restrict__ W1, const float* __restrict__ b1,
           const float* __restrict__ b2, const float* __restrict__ b3,
           const float* __restrict__ W4, const float* __restrict__ b4,
           const float* __restrict__ W5, const float* __restrict__ b5,
           const float* __restrict__ Wa, const float* __restrict__ ba,
           const float* __restrict__ Wo, const float* __restrict__ bo,
           float* __restrict__ out)
{
    extern __shared__ char smc[];
    float* smf = (float*)smc;
    const uint32_t sb = smem_u32(smc);

    const int bm   = blockIdx.x;         // centers 2bm, 2bm+1
    const int tid  = threadIdx.x;
    const int warp = tid >> 5;
    const int lane = tid & 31;
    const int gid  = lane >> 2;          // groupID (row within fragment)
    const int tq   = lane & 3;           // thread-in-group (col pair)
    const int r0   = warp * 16;          // this warp's M rows

    float* s_red  = smf + RED_B  / 4;
    float* s_hmax = smf + HMAX_B / 4;
    float* s_h4   = smf + H4_B   / 4;
    float* s_h5   = smf + H5_B   / 4;
    float* s_g    = smf + GXYZ_B / 4;
    float* s_W1   = smf + W1S_B  / 4;
    float* s_b1   = smf + B1S_B  / 4;
    float* s_b2   = smf + B2S_B  / 4;
    float* s_b3   = smf + B3S_B  / 4;

    // prefetch B2t hi/lo into padded SMEM (128 rows x 8 x 16B each)
    for (int e = tid; e < 1024; e += 256) {
        const int r = e >> 3, c = e & 7;
        cp16(sb + B2HI_B + r * 144 + c * 16, g_B2thi + r * 128 + c * 16);
        cp16(sb + B2LO_B + r * 144 + c * 16, g_B2tlo + r * 128 + c * 16);
    }
    CP_COMMIT();

    // small params + gather
    if (tid < 192) s_W1[tid] = W1[tid];
    if (tid < 64)  s_b1[tid] = b1[tid];
    if (tid < 128) s_b2[tid] = b2[tid];
    s_b3[tid] = b3[tid];
    if (tid < 128) {
        const int center = tid >> 6, s = tid & 63;
        const int cidx = bm * 2 + center;
        const int bb = cidx >> 9, mm = cidx & (MCL - 1);
        const float* xb = xyz + (size_t)bb * NPTS * 3;
        const int p = g_idx[(size_t)cidx * NSAMP + s];
        s_g[tid * 3 + 0] = (xb[p * 3 + 0] - xb[mm * 3 + 0]) * 0.5f;
        s_g[tid * 3 + 1] = (xb[p * 3 + 1] - xb[mm * 3 + 1]) * 0.5f;
        s_g[tid * 3 + 2] = (xb[p * 3 + 2] - xb[mm * 3 + 2]) * 0.5f;
    }
    __syncthreads();

    // ---- h1 = relu(g@W1+b1) -> A2 hi/lo (bf16, padded stride 144 B) ----
    {
        const int r = tid >> 1, c0 = (tid & 1) * 32;
        const float g0 = s_g[r * 3 + 0], g1 = s_g[r * 3 + 1], g2 = s_g[r * 3 + 2];
        #pragma unroll
        for (int q = 0; q < 16; q++) {
            const int c = c0 + q * 2;
            float v0 = fmaxf(s_b1[c]     + g0 * s_W1[c]     + g1 * s_W1[64 + c]     + g2 * s_W1[128 + c],     0.0f);
            float v1 = fmaxf(s_b1[c + 1] + g0 * s_W1[c + 1] + g1 * s_W1[64 + c + 1] + g2 * s_W1[128 + c + 1], 0.0f);
            uint32_t hw, lw;
            split2(v0, v1, hw, lw);
            *(uint32_t*)(smc + A2HI_B + r * 144 + c * 2) = hw;
            *(uint32_t*)(smc + A2LO_B + r * 144 + c * 2) = lw;
        }
    }
    CP_WAIT(0);
    __syncthreads();

    // ---- h2: per-warp C[16,128] = A2[16,64] @ W2, 3-pass hi/lo ----
    {
        float acc[16][4];
        #pragma unroll
        for (int t = 0; t < 16; t++)
            #pragma unroll
            for (int j = 0; j < 4; j++) acc[t][j] = 0.0f;

        #pragma unroll
        for (int k = 0; k < 4; k++) {
            const int kb = k * 16;
            const uint32_t o00 = (uint32_t)((r0 + gid) * 144 + (kb + tq * 2) * 2);
            const uint32_t o10 = o00 + 8 * 144;
            uint32_t ah[4], al[4];
            ah[0] = *(const uint32_t*)(smc + A2HI_B + o00);
            ah[1] = *(const uint32_t*)(smc + A2HI_B + o10);
            ah[2] = *(const uint32_t*)(smc + A2HI_B + o00 + 16);
            ah[3] = *(const uint32_t*)(smc + A2HI_B + o10 + 16);
            al[0] = *(const uint32_t*)(smc + A2LO_B + o00);
            al[1] = *(const uint32_t*)(smc + A2LO_B + o10);
            al[2] = *(const uint32_t*)(smc + A2LO_B + o00 + 16);
            al[3] = *(const uint32_t*)(smc + A2LO_B + o10 + 16);
            #pragma unroll
            for (int t = 0; t < 16; t++) {
                const uint32_t bo = (uint32_t)((t * 8 + gid) * 144 + (kb + tq * 2) * 2);
                uint32_t bh[2], bl[2];
                bh[0] = *(const uint32_t*)(smc + B2HI_B + bo);
                bh[1] = *(const uint32_t*)(smc + B2HI_B + bo + 16);
                bl[0] = *(const uint32_t*)(smc + B2LO_B + bo);
                bl[1] = *(const uint32_t*)(smc + B2LO_B + bo + 16);
                mma16816(acc[t], ah, bh);
                mma16816(acc[t], ah, bl);
                mma16816(acc[t], al, bh);
            }
        }

        // epilogue: +b2, relu, split -> A3 hi/lo (stride 272 B)
        #pragma unroll
        for (int t = 0; t < 16; t++) {
            const int n0 = t * 8 + tq * 2;
            const float bb0 = s_b2[n0], bb1 = s_b2[n0 + 1];
            float v00 = fmaxf(acc[t][0] + bb0, 0.0f), v01 = fmaxf(acc[t][1] + bb1, 0.0f);
            float v10 = fmaxf(acc[t][2] + bb0, 0.0f), v11 = fmaxf(acc[t][3] + bb1, 0.0f);
            uint32_t h0, l0, h1, l1;
            split2(v00, v01, h0, l0);
            split2(v10, v11, h1, l1);
            const uint32_t off0 = (uint32_t)((r0 + gid) * 272 + n0 * 2);
            const uint32_t off1 = off0 + 8 * 272;
            *(uint32_t*)(smc + A3HI_B + off0) = h0;
            *(uint32_t*)(smc + A3LO_B + off0) = l0;
            *(uint32_t*)(smc + A3HI_B + off1) = h1;
            *(uint32_t*)(smc + A3LO_B + off1) = l1;
        }
    }
    __syncthreads();   // region1 free, A3 published

    // issue B3 chunks 0,1 (each: 64 rows x 16 x 16B, hi+lo)
    #pragma unroll
    for (int cc = 0; cc < 2; cc++) {
        const uint32_t bufb = sb + (cc ? BUF1_B : BUF0_B);
        for (int e = tid; e < 1024; e += 256) {
            const int r = e >> 4, c4 = e & 15;
            cp16(bufb + r * 272 + c4 * 16,         g_B3thi + (size_t)(cc * 64 + r) * 256 + c4 * 16);
            cp16(bufb + 17408 + r * 272 + c4 * 16, g_B3tlo + (size_t)(cc * 64 + r) * 256 + c4 * 16);
        }
        CP_COMMIT();
    }

    // ---- h3: 4 N-chunks of 64; fused max over warp's 16 rows ----
    for (int c = 0; c < 4; c++) {
        if (c < 3) { CP_WAIT(1); } else { CP_WAIT(0); }
        __syncthreads();
        const char* buf = smc + ((c & 1) ? BUF1_B : BUF0_B);

        float acc[8][4];
        #pragma unroll
        for (int t = 0; t < 8; t++)
            #pragma unroll
            for (int j = 0; j < 4; j++) acc[t][j] = 0.0f;

        #pragma unroll
        for (int k = 0; k < 8; k++) {
            const int kb = k * 16;
            const uint32_t o00 = (uint32_t)((r0 + gid) * 272 + (kb + tq * 2) * 2);
            const uint32_t o10 = o00 + 8 * 272;
            uint32_t ah[4], al[4];
            ah[0] = *(const uint32_t*)(smc + A3HI_B + o00);
            ah[1] = *(const uint32_t*)(smc + A3HI_B + o10);
            ah[2] = *(const uint32_t*)(smc + A3HI_B + o00 + 16);
            ah[3] = *(const uint32_t*)(smc + A3HI_B + o10 + 16);
            al[0] = *(const uint32_t*)(smc + A3LO_B + o00);
            al[1] = *(const uint32_t*)(smc + A3LO_B + o10);
            al[2] = *(const uint32_t*)(smc + A3LO_B + o00 + 16);
            al[3] = *(const uint32_t*)(smc + A3LO_B + o10 + 16);
            #pragma unroll
            for (int t = 0; t < 8; t++) {
                const uint32_t bo = (uint32_t)((t * 8 + gid) * 272 + (kb + tq * 2) * 2);
                uint32_t bh[2], bl[2];
                bh[0] = *(const uint32_t*)(buf + bo);
                bh[1] = *(const uint32_t*)(buf + bo + 16);
                bl[0] = *(const uint32_t*)(buf + 17408 + bo);
                bl[1] = *(const uint32_t*)(buf + 17408 + bo + 16);
                mma16816(acc[t], ah, bh);
                mma16816(acc[t], ah, bl);
                mma16816(acc[t], al, bh);
            }
        }

        // max over this warp's 16 rows -> s_red[warp][c*64 + n]
        #pragma unroll
        for (int t = 0; t < 8; t++) {
            float v0 = fmaxf(acc[t][0], acc[t][2]);
            float v1 = fmaxf(acc[t][1], acc[t][3]);
            #pragma unroll
            for (int off = 4; off < 32; off <<= 1) {
                v0 = fmaxf(v0, __shfl_xor_sync(0xffffffffu, v0, off));
                v1 = fmaxf(v1, __shfl_xor_sync(0xffffffffu, v1, off));
            }
            if (lane < 4) {
                s_red[warp * 256 + c * 64 + t * 8 + tq * 2]     = v0;
                s_red[warp * 256 + c * 64 + t * 8 + tq * 2 + 1] = v1;
            }
        }

        if (c + 2 < 4) {
            __syncthreads();   // all warps done reading buf (c&1)
            const uint32_t bufb = sb + ((c & 1) ? BUF1_B : BUF0_B);
            for (int e = tid; e < 1024; e += 256) {
                const int r = e >> 4, c4 = e & 15;
                cp16(bufb + r * 272 + c4 * 16,         g_B3thi + (size_t)((c + 2) * 64 + r) * 256 + c4 * 16);
                cp16(bufb + 17408 + r * 272 + c4 * 16, g_B3tlo + (size_t)((c + 2) * 64 + r) * 256 + c4 * 16);
            }
            CP_COMMIT();
        }
    }
    __syncthreads();

    // ---- combine per-center warp maxes, +b3, relu -> s_hmax[2][256] ----
    {
        float m0v = s_red[0 * 256 + tid];
        float m1v = s_red[4 * 256 + tid];
        #pragma unroll
        for (int w = 1; w < 4; w++) {
            m0v = fmaxf(m0v, s_red[w * 256 + tid]);
            m1v = fmaxf(m1v, s_red[(4 + w) * 256 + tid]);
        }
        s_hmax[tid]       = fmaxf(m0v + s_b3[tid], 0.0f);
        s_hmax[256 + tid] = fmaxf(m1v + s_b3[tid], 0.0f);
    }
    __syncthreads();

    // ---- h4 = hmax @ W4 + b4 (fp32 exact): 2 centers x 128 ----
    {
        const int center = tid >> 7, o = tid & 127;
        float acc = b4[o];
        const float* hm = s_hmax + center * 256;
        #pragma unroll 8
        for (int e = 0; e < 256; e++)
            acc = fmaf(hm[e], W4[(size_t)e * 128 + o], acc);
        s_h4[center * 128 + o] = acc;
    }
    __syncthreads();

    // ---- h5 = h4 @ W5 + b5: 2 centers x 64 ----
    if (tid < 128) {
        const int center = tid >> 6, o = tid & 63;
        float acc = b5[o];
        const float* h4p = s_h4 + center * 128;
        #pragma unroll 8
        for (int d = 0; d < 128; d++)
            acc = fmaf(h4p[d], W5[(size_t)d * 64 + o], acc);
        s_h5[center * 64 + o] = acc;
    }
    __syncthreads();

    // ---- heads ----
    if (warp < 2) {
        const int center = warp;
        const float h5a = s_h5[center * 64 + lane], h5b = s_h5[center * 64 + lane + 32];
        float pa = h5a * Wa[lane]         + h5b * Wa[lane + 32];
        float p0 = h5a * Wo[lane * 2 + 0] + h5b * Wo[(lane + 32) * 2 + 0];
        float p1 = h5a * Wo[lane * 2 + 1] + h5b * Wo[(lane + 32) * 2 + 1];
        #pragma unroll
        for (int off = 16; off; off >>= 1) {
            pa += __shfl_xor_sync(0xffffffffu, pa, off);
            p0 += __shfl_xor_sync(0xffffffffu, p0, off);
            p1 += __shfl_xor_sync(0xffffffffu, p1, off);
        }
        if (lane == 0) {
            const float x  = pa + ba[0];
            const float att = fmaxf(x, 0.0f) + log1pf(expf(-fabsf(x)));
            float o0 = p0 + bo[0];
            float o1 = p1 + bo[1];
            const float inv = 1.0f / sqrtf(fmaxf(o0 * o0 + o1 * o1, 1e-8f));
            o0 *= inv; o1 *= inv;
            out[OUT_ATT + bm * 2 + center] = att;
            out[OUT_ORI + bm * 2 + center] = atan2f(o1, o0);
        }
    }
}

// =====================================================================
extern "C" void kernel_launch(void* const* d_in, const int* in_sizes, int n_in,
                              void* d_out, int out_size)
{
    const float* xyz = (const float*)d_in[0];
    const float* W1  = (const float*)d_in[1];
    const float* b1  = (const float*)d_in[2];
    const float* W2  = (const float*)d_in[3];
    const float* b2  = (const float*)d_in[4];
    const float* W3  = (const float*)d_in[5];
    const float* b3  = (const float*)d_in[6];
    const float* W4  = (const float*)d_in[7];
    const float* b4  = (const float*)d_in[8];
    const float* W5  = (const float*)d_in[9];
    const float* b5  = (const float*)d_in[10];
    const float* Wa  = (const float*)d_in[11];
    const float* ba  = (const float*)d_in[12];
    const float* Wo  = (const float*)d_in[13];
    const float* bo  = (const float*)d_in[14];
    float* out = (float*)d_out;

    const int smem1 = NPTS * 3 * 4 + 8 * NSAMP * 4;   // 100352 B

    cudaFuncSetAttribute(ball_query_kernel,
                         cudaFuncAttributeMaxDynamicSharedMemorySize, smem1);
    cudaFuncSetAttribute(mlp_kernel,
                         cudaFuncAttributeMaxDynamicSharedMemorySize, SMEM_MLP);

    prep_weights<<<160, 256>>>(W2, W3);
    ball_query_kernel<<<BATCH * 16, 256, smem1>>>(xyz, out);
    mlp_kernel<<<BATCH * MCL / 2, 256, SMEM_MLP>>>(xyz, W1, b1, b2, b3,
                                                   W4, b4, W5, b5, Wa, ba, Wo, bo, out);
}

// round 15
// speedup vs baseline: 1.3938x; 1.0047x over previous
#include <cuda_runtime.h>
#include <cuda_bf16.h>
#include <math.h>
#include <stdint.h>

#define BATCH 8
#define NPTS  8192
#define MCL   512
#define NSAMP 64

#define OUT_XYZ 0
#define OUT_IDX (BATCH*MCL*3)
#define OUT_ATT (OUT_IDX + BATCH*MCL*NSAMP)
#define OUT_ORI (OUT_ATT + BATCH*MCL)

__device__ int g_idx[BATCH * MCL * NSAMP];
// transposed bf16 hi/lo weight images: B2t[n][k] (128x64), B3t[n][k] (256x128)
__device__ unsigned char g_B2thi[16384];
__device__ unsigned char g_B2tlo[16384];
__device__ unsigned char g_B3thi[65536];
__device__ unsigned char g_B3tlo[65536];

// ---------------- helpers ----------------
__device__ __forceinline__ uint32_t smem_u32(const void* p) {
    uint32_t a;
    asm("{ .reg .u64 t; cvta.to.shared.u64 t, %1; cvt.u32.u64 %0, t; }" : "=r"(a) : "l"(p));
    return a;
}
__device__ __forceinline__ void cp16(uint32_t dst, const void* src) {
    asm volatile("cp.async.ca.shared.global [%0], [%1], 16;" :: "r"(dst), "l"(src));
}
#define CP_COMMIT() asm volatile("cp.async.commit_group;")
#define CP_WAIT(n)  asm volatile("cp.async.wait_group %0;" :: "n"(n))

__device__ __forceinline__ void mma16816(float* d, const uint32_t* a, const uint32_t* b) {
    asm volatile("mma.sync.aligned.m16n8k16.row.col.f32.bf16.bf16.f32 "
        "{%0,%1,%2,%3}, {%4,%5,%6,%7}, {%8,%9}, {%0,%1,%2,%3};"
        : "+f"(d[0]), "+f"(d[1]), "+f"(d[2]), "+f"(d[3])
        : "r"(a[0]), "r"(a[1]), "r"(a[2]), "r"(a[3]), "r"(b[0]), "r"(b[1]));
}
__device__ __forceinline__ void split2(float v0, float v1, uint32_t& hi, uint32_t& lo) {
    __nv_bfloat16 h0 = __float2bfloat16_rn(v0);
    __nv_bfloat16 h1 = __float2bfloat16_rn(v1);
    __nv_bfloat16 l0 = __float2bfloat16_rn(v0 - __bfloat162float(h0));
    __nv_bfloat16 l1 = __float2bfloat16_rn(v1 - __bfloat162float(h1));
    hi = (uint32_t)__bfloat16_as_ushort(h0) | ((uint32_t)__bfloat16_as_ushort(h1) << 16);
    lo = (uint32_t)__bfloat16_as_ushort(l0) | ((uint32_t)__bfloat16_as_ushort(l1) << 16);
}

// SMEM byte offsets (mlp kernel). Padded strides: A2/B2t rows 144 B (72 bf16),
// A3/B3 rows 272 B (136 bf16) — conflict-free fragment LDS.
#define A2HI_B   0          // 128*144 = 18432   (region1: reused as B3 bufs)
#define A2LO_B   18432
#define B2HI_B   36864
#define B2LO_B   55296      // region1 end 73728
#define BUF0_B   0          // B3 chunk buf0: hi 0..17408, lo 17408..34816
#define BUF1_B   34816      // buf1: hi..52224, lo..69632
#define A3HI_B   73728      // 128*272 = 34816
#define A3LO_B   108544     // end 143360
#define RED_B    143360     // 8*256 f = 8192
#define HMAX_B   151552     // 2*256 f
#define H4_B     153600     // 2*128 f
#define H5_B     154624     // 2*64 f
#define GXYZ_B   155136     // 128*3 f
#define W1S_B    156672     // 192 f
#define B1S_B    157440     // 64 f
#define B2S_B    157696     // 128 f
#define B3S_B    158208     // 256 f
#define SMEM_MLP 159232

// =====================================================================
// Kernel 0: build transposed bf16 hi/lo weight images
// =====================================================================
__global__ void __launch_bounds__(256)
prep_weights(const float* __restrict__ W2, const float* __restrict__ W3)
{
    const int i = blockIdx.x * 256 + threadIdx.x;
    if (i < 8192) {                       // B2t[n][k] = W2[k][n], n<128, k<64
        const int n = i >> 6, k = i & 63;
        const float v = W2[k * 128 + n];
        __nv_bfloat16 h = __float2bfloat16_rn(v);
        __nv_bfloat16 l = __float2bfloat16_rn(v - __bfloat162float(h));
        *(unsigned short*)(g_B2thi + (n * 64 + k) * 2) = __bfloat16_as_ushort(h);
        *(unsigned short*)(g_B2tlo + (n * 64 + k) * 2) = __bfloat16_as_ushort(l);
    } else if (i < 8192 + 32768) {        // B3t[n][k] = W3[k][n], n<256, k<128
        const int e = i - 8192;
        const int n = e >> 7, k = e & 127;
        const float v = W3[k * 256 + n];
        __nv_bfloat16 h = __float2bfloat16_rn(v);
        __nv_bfloat16 l = __float2bfloat16_rn(v - __bfloat162float(h));
        *(unsigned short*)(g_B3thi + (n * 128 + k) * 2) = __bfloat16_as_ushort(h);
        *(unsigned short*)(g_B3tlo + (n * 128 + k) * 2) = __bfloat16_as_ushort(l);
    }
}

// =====================================================================
// Kernel 1: ball query (unchanged — passes)
// =====================================================================
__global__ void __launch_bounds__(256)
ball_query_kernel(const float* __restrict__ xyz, float* __restrict__ out)
{
    extern __shared__ float smem[];
    float* sxyz = smem;
    int*   sidx = (int*)(smem + NPTS * 3);

    const int b     = blockIdx.x >> 4;
    const int chunk = blockIdx.x & 15;
    const float* xb = xyz + (size_t)b * NPTS * 3;

    const float4* xb4 = (const float4*)xb;
    for (int i = threadIdx.x; i < NPTS * 3 / 4; i += 256)
        ((float4*)sxyz)[i] = xb4[i];
    __syncthreads();

    const int m0 = chunk * 32;
    for (int i = threadIdx.x; i < 96; i += 256)
        out[OUT_XYZ + ((size_t)b * MCL + m0) * 3 + i] = sxyz[m0 * 3 + i];

    const int warp = threadIdx.x >> 5;
    const int lane = threadIdx.x & 31;
    int* wbuf = sidx + warp * NSAMP;

    for (int mi = warp; mi < 32; mi += 8) {
        const int m = m0 + mi;
        const float cx = sxyz[m * 3 + 0];
        const float cy = sxyz[m * 3 + 1];
        const float cz = sxyz[m * 3 + 2];
        int cnt = 0;
        for (int j = 0; j < NPTS; j += 32) {
            const int p = j + lane;
            float dx = __fsub_rn(cx, sxyz[p * 3 + 0]);
            float dy = __fsub_rn(cy, sxyz[p * 3 + 1]);
            float dz = __fsub_rn(cz, sxyz[p * 3 + 2]);
            float d2 = __fadd_rn(__fadd_rn(__fmul_rn(dx, dx), __fmul_rn(dy, dy)),
                                 __fmul_rn(dz, dz));
            bool valid = d2 < 4.0f;
            unsigned msk = __ballot_sync(0xffffffffu, valid);
            int pos = cnt + __popc(msk & ((1u << lane) - 1u));
            if (valid && pos < NSAMP) wbuf[pos] = p;
            cnt += __popc(msk);
            if (cnt >= NSAMP) break;
        }
        __syncwarp();
        const int first = wbuf[0];
        const int c = cnt < NSAMP ? cnt : NSAMP;
        const long base = ((long)b * MCL + m) * NSAMP;
        for (int k = lane; k < NSAMP; k += 32) {
            const int v = (k < c) ? wbuf[k] : first;
            g_idx[base + k] = v;
            out[OUT_IDX + base + k] = (float)v;
        }
        __syncwarp();
    }
}

// =====================================================================
// Kernel 2: fused MLP on mma.sync bf16 (hi/lo split, fp32 accumulate).
// 2 centers/block (M=128), 8 warps x 16-row tiles.
// h2: 16x128x64 per warp. h3: 4 N-chunks of 64, K=128, W3 streamed.
// =====================================================================
__global__ void __launch_bounds__(256, 1)
mlp_kernel(const float* __restrict__ xyz,
           const float* __restrict__ W1, const float* __restrict__ b1,
           const float* __restrict__ b2, const float* __restrict__ b3,
           const float* __restrict__ W4, const float* __restrict__ b4,
           const float* __restrict__ W5, const float* __restrict__ b5,
           const float* __restrict__ Wa, const float* __restrict__ ba,
           const float* __restrict__ Wo, const float* __restrict__ bo,
           float* __restrict__ out)
{
    extern __shared__ char smc[];
    float* smf = (float*)smc;
    const uint32_t sb = smem_u32(smc);

    const int bm   = blockIdx.x;         // centers 2bm, 2bm+1
    const int tid  = threadIdx.x;
    const int warp = tid >> 5;
    const int lane = tid & 31;
    const int gid  = lane >> 2;          // groupID (row within fragment)
    const int tq   = lane & 3;           // thread-in-group (col pair)
    const int r0   = warp * 16;          // this warp's M rows

    float* s_red  = smf + RED_B  / 4;
    float* s_hmax = smf + HMAX_B / 4;
    float* s_h4   = smf + H4_B   / 4;
    float* s_h5   = smf + H5_B   / 4;
    float* s_g    = smf + GXYZ_B / 4;
    float* s_W1   = smf + W1S_B  / 4;
    float* s_b1   = smf + B1S_B  / 4;
    float* s_b2   = smf + B2S_B  / 4;
    float* s_b3   = smf + B3S_B  / 4;

    // prefetch B2t hi/lo into padded SMEM (128 rows x 8 x 16B each)
    for (int e = tid; e < 1024; e += 256) {
        const int r = e >> 3, c = e & 7;
        cp16(sb + B2HI_B + r * 144 + c * 16, g_B2thi + r * 128 + c * 16);
        cp16(sb + B2LO_B + r * 144 + c * 16, g_B2tlo + r * 128 + c * 16);
    }
    CP_COMMIT();

    // small params + gather
    if (tid < 192) s_W1[tid] = W1[tid];
    if (tid < 64)  s_b1[tid] = b1[tid];
    if (tid < 128) s_b2[tid] = b2[tid];
    s_b3[tid] = b3[tid];
    if (tid < 128) {
        const int center = tid >> 6, s = tid & 63;
        const int cidx = bm * 2 + center;
        const int bb = cidx >> 9, mm = cidx & (MCL - 1);
        const float* xb = xyz + (size_t)bb * NPTS * 3;
        const int p = g_idx[(size_t)cidx * NSAMP + s];
        s_g[tid * 3 + 0] = (xb[p * 3 + 0] - xb[mm * 3 + 0]) * 0.5f;
        s_g[tid * 3 + 1] = (xb[p * 3 + 1] - xb[mm * 3 + 1]) * 0.5f;
        s_g[tid * 3 + 2] = (xb[p * 3 + 2] - xb[mm * 3 + 2]) * 0.5f;
    }
    __syncthreads();

    // ---- h1 = relu(g@W1+b1) -> A2 hi/lo (bf16, padded stride 144 B) ----
    {
        const int r = tid >> 1, c0 = (tid & 1) * 32;
        const float g0 = s_g[r * 3 + 0], g1 = s_g[r * 3 + 1], g2 = s_g[r * 3 + 2];
        #pragma unroll
        for (int q = 0; q < 16; q++) {
            const int c = c0 + q * 2;
            float v0 = fmaxf(s_b1[c]     + g0 * s_W1[c]     + g1 * s_W1[64 + c]     + g2 * s_W1[128 + c],     0.0f);
            float v1 = fmaxf(s_b1[c + 1] + g0 * s_W1[c + 1] + g1 * s_W1[64 + c + 1] + g2 * s_W1[128 + c + 1], 0.0f);
            uint32_t hw, lw;
            split2(v0, v1, hw, lw);
            *(uint32_t*)(smc + A2HI_B + r * 144 + c * 2) = hw;
            *(uint32_t*)(smc + A2LO_B + r * 144 + c * 2) = lw;
        }
    }
    CP_WAIT(0);
    __syncthreads();

    // ---- h2: per-warp C[16,128] = A2[16,64] @ W2, 3-pass hi/lo ----
    {
        float acc[16][4];
        #pragma unroll
        for (int t = 0; t < 16; t++)
            #pragma unroll
            for (int j = 0; j < 4; j++) acc[t][j] = 0.0f;

        #pragma unroll
        for (int k = 0; k < 4; k++) {
            const int kb = k * 16;
            const uint32_t o00 = (uint32_t)((r0 + gid) * 144 + (kb + tq * 2) * 2);
            const uint32_t o10 = o00 + 8 * 144;
            uint32_t ah[4], al[4];
            ah[0] = *(const uint32_t*)(smc + A2HI_B + o00);
            ah[1] = *(const uint32_t*)(smc + A2HI_B + o10);
            ah[2] = *(const uint32_t*)(smc + A2HI_B + o00 + 16);
            ah[3] = *(const uint32_t*)(smc + A2HI_B + o10 + 16);
            al[0] = *(const uint32_t*)(smc + A2LO_B + o00);
            al[1] = *(const uint32_t*)(smc + A2LO_B + o10);
            al[2] = *(const uint32_t*)(smc + A2LO_B + o00 + 16);
            al[3] = *(const uint32_t*)(smc + A2LO_B + o10 + 16);
            #pragma unroll
            for (int t = 0; t < 16; t++) {
                const uint32_t bo = (uint32_t)((t * 8 + gid) * 144 + (kb + tq * 2) * 2);
                uint32_t bh[2], bl[2];
                bh[0] = *(const uint32_t*)(smc + B2HI_B + bo);
                bh[1] = *(const uint32_t*)(smc + B2HI_B + bo + 16);
                bl[0] = *(const uint32_t*)(smc + B2LO_B + bo);
                bl[1] = *(const uint32_t*)(smc + B2LO_B + bo + 16);
                mma16816(acc[t], ah, bh);
                mma16816(acc[t], ah, bl);
                mma16816(acc[t], al, bh);
            }
        }

        // epilogue: +b2, relu, split -> A3 hi/lo (stride 272 B)
        #pragma unroll
        for (int t = 0; t < 16; t++) {
            const int n0 = t * 8 + tq * 2;
            const float bb0 = s_b2[n0], bb1 = s_b2[n0 + 1];
            float v00 = fmaxf(acc[t][0] + bb0, 0.0f), v01 = fmaxf(acc[t][1] + bb1, 0.0f);
            float v10 = fmaxf(acc[t][2] + bb0, 0.0f), v11 = fmaxf(acc[t][3] + bb1, 0.0f);
            uint32_t h0, l0, h1, l1;
            split2(v00, v01, h0, l0);
            split2(v10, v11, h1, l1);
            const uint32_t off0 = (uint32_t)((r0 + gid) * 272 + n0 * 2);
            const uint32_t off1 = off0 + 8 * 272;
            *(uint32_t*)(smc + A3HI_B + off0) = h0;
            *(uint32_t*)(smc + A3LO_B + off0) = l0;
            *(uint32_t*)(smc + A3HI_B + off1) = h1;
            *(uint32_t*)(smc + A3LO_B + off1) = l1;
        }
    }
    __syncthreads();   // region1 free, A3 published

    // issue B3 chunks 0,1 (each: 64 rows x 16 x 16B, hi+lo)
    #pragma unroll
    for (int cc = 0; cc < 2; cc++) {
        const uint32_t bufb = sb + (cc ? BUF1_B : BUF0_B);
        for (int e = tid; e < 1024; e += 256) {
            const int r = e >> 4, c4 = e & 15;
            cp16(bufb + r * 272 + c4 * 16,         g_B3thi + (size_t)(cc * 64 + r) * 256 + c4 * 16);
            cp16(bufb + 17408 + r * 272 + c4 * 16, g_B3tlo + (size_t)(cc * 64 + r) * 256 + c4 * 16);
        }
        CP_COMMIT();
    }

    // ---- h3: 4 N-chunks of 64; fused max over warp's 16 rows ----
    for (int c = 0; c < 4; c++) {
        if (c < 3) { CP_WAIT(1); } else { CP_WAIT(0); }
        __syncthreads();
        const char* buf = smc + ((c & 1) ? BUF1_B : BUF0_B);

        float acc[8][4];
        #pragma unroll
        for (int t = 0; t < 8; t++)
            #pragma unroll
            for (int j = 0; j < 4; j++) acc[t][j] = 0.0f;

        #pragma unroll
        for (int k = 0; k < 8; k++) {
            const int kb = k * 16;
            const uint32_t o00 = (uint32_t)((r0 + gid) * 272 + (kb + tq * 2) * 2);
            const uint32_t o10 = o00 + 8 * 272;
            uint32_t ah[4], al[4];
            ah[0] = *(const uint32_t*)(smc + A3HI_B + o00);
            ah[1] = *(const uint32_t*)(smc + A3HI_B + o10);
            ah[2] = *(const uint32_t*)(smc + A3HI_B + o00 + 16);
            ah[3] = *(const uint32_t*)(smc + A3HI_B + o10 + 16);
            al[0] = *(const uint32_t*)(smc + A3LO_B + o00);
            al[1] = *(const uint32_t*)(smc + A3LO_B + o10);
            al[2] = *(const uint32_t*)(smc + A3LO_B + o00 + 16);
            al[3] = *(const uint32_t*)(smc + A3LO_B + o10 + 16);
            #pragma unroll
            for (int t = 0; t < 8; t++) {
                const uint32_t bo = (uint32_t)((t * 8 + gid) * 272 + (kb + tq * 2) * 2);
                uint32_t bh[2], bl[2];
                bh[0] = *(const uint32_t*)(buf + bo);
                bh[1] = *(const uint32_t*)(buf + bo + 16);
                bl[0] = *(const uint32_t*)(buf + 17408 + bo);
                bl[1] = *(const uint32_t*)(buf + 17408 + bo + 16);
                mma16816(acc[t], ah, bh);
                mma16816(acc[t], ah, bl);
                mma16816(acc[t], al, bh);
            }
        }

        // max over this warp's 16 rows -> s_red[warp][c*64 + n]
        #pragma unroll
        for (int t = 0; t < 8; t++) {
            float v0 = fmaxf(acc[t][0], acc[t][2]);
            float v1 = fmaxf(acc[t][1], acc[t][3]);
            #pragma unroll
            for (int off = 4; off < 32; off <<= 1) {
                v0 = fmaxf(v0, __shfl_xor_sync(0xffffffffu, v0, off));
                v1 = fmaxf(v1, __shfl_xor_sync(0xffffffffu, v1, off));
            }
            if (lane < 4) {
                s_red[warp * 256 + c * 64 + t * 8 + tq * 2]     = v0;
                s_red[warp * 256 + c * 64 + t * 8 + tq * 2 + 1] = v1;
            }
        }

        if (c + 2 < 4) {
            __syncthreads();   // all warps done reading buf (c&1)
            const uint32_t bufb = sb + ((c & 1) ? BUF1_B : BUF0_B);
            for (int e = tid; e < 1024; e += 256) {
                const int r = e >> 4, c4 = e & 15;
                cp16(bufb + r * 272 + c4 * 16,         g_B3thi + (size_t)((c + 2) * 64 + r) * 256 + c4 * 16);
                cp16(bufb + 17408 + r * 272 + c4 * 16, g_B3tlo + (size_t)((c + 2) * 64 + r) * 256 + c4 * 16);
            }
            CP_COMMIT();
        }
    }
    __syncthreads();

    // ---- combine per-center warp maxes, +b3, relu -> s_hmax[2][256] ----
    {
        float m0v = s_red[0 * 256 + tid];
        float m1v = s_red[4 * 256 + tid];
        #pragma unroll
        for (int w = 1; w < 4; w++) {
            m0v = fmaxf(m0v, s_red[w * 256 + tid]);
            m1v = fmaxf(m1v, s_red[(4 + w) * 256 + tid]);
        }
        s_hmax[tid]       = fmaxf(m0v + s_b3[tid], 0.0f);
        s_hmax[256 + tid] = fmaxf(m1v + s_b3[tid], 0.0f);
    }
    __syncthreads();

    // ---- h4 = hmax @ W4 + b4 (fp32 exact): 2 centers x 128 ----
    {
        const int center = tid >> 7, o = tid & 127;
        float acc = b4[o];
        const float* hm = s_hmax + center * 256;
        #pragma unroll 8
        for (int e = 0; e < 256; e++)
            acc = fmaf(hm[e], W4[(size_t)e * 128 + o], acc);
        s_h4[center * 128 + o] = acc;
    }
    __syncthreads();

    // ---- h5 = h4 @ W5 + b5: 2 centers x 64 ----
    if (tid < 128) {
        const int center = tid >> 6, o = tid & 63;
        float acc = b5[o];
        const float* h4p = s_h4 + center * 128;
        #pragma unroll 8
        for (int d = 0; d < 128; d++)
            acc = fmaf(h4p[d], W5[(size_t)d * 64 + o], acc);
        s_h5[center * 64 + o] = acc;
    }
    __syncthreads();

    // ---- heads ----
    if (warp < 2) {
        const int center = warp;
        const float h5a = s_h5[center * 64 + lane], h5b = s_h5[center * 64 + lane + 32];
        float pa = h5a * Wa[lane]         + h5b * Wa[lane + 32];
        float p0 = h5a * Wo[lane * 2 + 0] + h5b * Wo[(lane + 32) * 2 + 0];
        float p1 = h5a * Wo[lane * 2 + 1] + h5b * Wo[(lane + 32) * 2 + 1];
        #pragma unroll
        for (int off = 16; off; off >>= 1) {
            pa += __shfl_xor_sync(0xffffffffu, pa, off);
            p0 += __shfl_xor_sync(0xffffffffu, p0, off);
            p1 += __shfl_xor_sync(0xffffffffu, p1, off);
        }
        if (lane == 0) {
            const float x  = pa + ba[0];
            const float att = fmaxf(x, 0.0f) + log1pf(expf(-fabsf(x)));
            float o0 = p0 + bo[0];
            float o1 = p1 + bo[1];
            const float inv = 1.0f / sqrtf(fmaxf(o0 * o0 + o1 * o1, 1e-8f));
            o0 *= inv; o1 *= inv;
            out[OUT_ATT + bm * 2 + center] = att;
            out[OUT_ORI + bm * 2 + center] = atan2f(o1, o0);
        }
    }
}

// =====================================================================
extern "C" void kernel_launch(void* const* d_in, const int* in_sizes, int n_in,
                              void* d_out, int out_size)
{
    const float* xyz = (const float*)d_in[0];
    const float* W1  = (const float*)d_in[1];
    const float* b1  = (const float*)d_in[2];
    const float* W2  = (const float*)d_in[3];
    const float* b2  = (const float*)d_in[4];
    const float* W3  = (const float*)d_in[5];
    const float* b3  = (const float*)d_in[6];
    const float* W4  = (const float*)d_in[7];
    const float* b4  = (const float*)d_in[8];
    const float* W5  = (const float*)d_in[9];
    const float* b5  = (const float*)d_in[10];
    const float* Wa  = (const float*)d_in[11];
    const float* ba  = (const float*)d_in[12];
    const float* Wo  = (const float*)d_in[13];
    const float* bo  = (const float*)d_in[14];
    float* out = (float*)d_out;

    const int smem1 = NPTS * 3 * 4 + 8 * NSAMP * 4;   // 100352 B

    cudaFuncSetAttribute(ball_query_kernel,
                         cudaFuncAttributeMaxDynamicSharedMemorySize, smem1);
    cudaFuncSetAttribute(mlp_kernel,
                         cudaFuncAttributeMaxDynamicSharedMemorySize, SMEM_MLP);

    prep_weights<<<160, 256>>>(W2, W3);
    ball_query_kernel<<<BATCH * 16, 256, smem1>>>(xyz, out);
    mlp_kernel<<<BATCH * MCL / 2, 256, SMEM_MLP>>>(xyz, W1, b1, b2, b3,
                                                   W4, b4, W5, b5, Wa, ba, Wo, bo, out);
}